// round 15
// baseline (speedup 1.0000x reference)
#include <cuda_runtime.h>
#include <cuda_bf16.h>
#include <math.h>
#include <stdint.h>

#define N_TOK 65536
#define DD 32
#define NH 8
#define NBLK 256
#define L2E 1.4426950408889634f

// ---------------- device scratch ----------------
__device__ unsigned long long g_sort[N_TOK];               // (key<<32)|idx, sorted
__device__ unsigned long long g_sort2[N_TOK];              // bucket-grouped
__device__ unsigned g_histc[64 * 2048];
__device__ unsigned g_bstart[2049];
__device__ unsigned g_cursor[2048];
__device__ float g_w2[16];
__device__ __align__(16) unsigned g_wqkvb[3 * 256 * 16];   // bf16x2 [w][o][16]
__device__ __align__(16) unsigned g_woutb[32 * 128];       // bf16x2 [o][128]
__device__ __align__(16) unsigned g_wffb[1024];            // bf16x2 ffn w1 [0,512) w2 [512,1024)
__device__ __align__(16) unsigned g_xnb[N_TOK * 16];       // bf16x2 xn, sorted token-major
__device__ __align__(16) unsigned g_attb[N_TOK * 128];     // bf16x2 [b][i][128] token-major
__device__ float g_p[N_TOK * 2];

// ---------------- helpers ----------------
__device__ __forceinline__ unsigned pack_bf16x2(float lo, float hi) {
    unsigned r;
    asm("cvt.rn.bf16x2.f32 %0, %1, %2;" : "=r"(r) : "f"(hi), "f"(lo));
    return r;
}
__device__ __forceinline__ unsigned smem_u32(const void* p) {
    unsigned a;
    asm("{ .reg .u64 t; cvta.to.shared.u64 t, %1; cvt.u32.u64 %0, t; }" : "=r"(a) : "l"(p));
    return a;
}
__device__ __forceinline__ float ex2f(float x) {
    float r; asm("ex2.approx.f32 %0, %1;" : "=f"(r) : "f"(x)); return r;
}
__device__ __forceinline__ void mma_bf16(float c[4], const unsigned a[4],
                                         unsigned b0, unsigned b1) {
    asm volatile("mma.sync.aligned.m16n8k16.row.col.f32.bf16.bf16.f32 "
                 "{%0,%1,%2,%3}, {%4,%5,%6,%7}, {%8,%9}, {%0,%1,%2,%3};"
                 : "+f"(c[0]), "+f"(c[1]), "+f"(c[2]), "+f"(c[3])
                 : "r"(a[0]), "r"(a[1]), "r"(a[2]), "r"(a[3]), "r"(b0), "r"(b1));
}
__device__ __forceinline__ void ldm_x4(unsigned r[4], unsigned addr) {
    asm volatile("ldmatrix.sync.aligned.m8n8.x4.shared.b16 {%0,%1,%2,%3}, [%4];"
                 : "=r"(r[0]), "=r"(r[1]), "=r"(r[2]), "=r"(r[3]) : "r"(addr));
}
__device__ __forceinline__ void ldm_x4t(unsigned r[4], unsigned addr) {
    asm volatile("ldmatrix.sync.aligned.m8n8.x4.trans.shared.b16 {%0,%1,%2,%3}, [%4];"
                 : "=r"(r[0]), "=r"(r[1]), "=r"(r[2]), "=r"(r[3]) : "r"(addr));
}

// ---------------- bucket sort ----------------
__global__ void __launch_bounds__(1024) sort_hist(const float* __restrict__ coords) {
    __shared__ unsigned hist[2048];
    int tid = threadIdx.x;
    hist[tid] = 0; hist[tid + 1024] = 0;
    __syncthreads();
    int gi = blockIdx.x * 1024 + tid;
    float v = coords[3 * gi];
    int b = (int)(v * 2048.f); if (b > 2047) b = 2047;
    atomicAdd(&hist[b], 1u);
    __syncthreads();
    g_histc[blockIdx.x * 2048 + tid] = hist[tid];
    g_histc[blockIdx.x * 2048 + tid + 1024] = hist[tid + 1024];
}

__global__ void __launch_bounds__(1024) sort_prefix_prep(
    const float* __restrict__ wq, const float* __restrict__ wk,
    const float* __restrict__ wv, const float* __restrict__ wout,
    const float* __restrict__ wrpe,
    const float* __restrict__ fw1, const float* __restrict__ fw2) {
    __shared__ unsigned tots[2048];
    __shared__ unsigned wsum[32];
    int tid = threadIdx.x;
    int lane = tid & 31, wid = tid >> 5;

    for (int gid = tid; gid < 16384; gid += 1024) {
        if (gid < 12288) {
            const float* src = (gid < 4096) ? wq : (gid < 8192) ? wk : wv;
            int r = gid & 4095; int o = r >> 4, c = r & 15;
            g_wqkvb[gid] = pack_bf16x2(src[o * 32 + 2 * c], src[o * 32 + 2 * c + 1]);
        } else {
            int r = gid - 12288; int o = r >> 7, c = r & 127;
            g_woutb[r] = pack_bf16x2(wout[o * 256 + 2 * c], wout[o * 256 + 2 * c + 1]);
        }
    }
    if (tid < 1024) {
        const float* srcf = (tid < 512) ? fw1 : fw2;
        int r = tid & 511;
        int o = r >> 4, c = r & 15;
        g_wffb[tid] = pack_bf16x2(srcf[o * 32 + 2 * c], srcf[o * 32 + 2 * c + 1]);
    }
    if (tid < 16) {
        int h = tid >> 1, c = tid & 1;
        float acc = 0.f;
        for (int d = 0; d < 32; d++)
            for (int w = 0; w < 8; w++) {
                float v = wrpe[(h * 32 + d) * 16 + c * 8 + w];
                acc += v * v;
            }
        g_w2[tid] = acc * (1.f / 256.f);
    }

    for (int b = tid; b < 2048; b += 1024) {
        unsigned t = 0;
        for (int c = 0; c < 64; c++) t += g_histc[c * 2048 + b];
        tots[b] = t;
    }
    __syncthreads();
    unsigned ps = tots[2 * tid] + tots[2 * tid + 1];
    unsigned v = ps;
    for (int o = 1; o < 32; o <<= 1) {
        unsigned n = __shfl_up_sync(~0u, v, o);
        if (lane >= o) v += n;
    }
    if (lane == 31) wsum[wid] = v;
    __syncthreads();
    if (wid == 0) {
        unsigned w = wsum[lane];
        unsigned vv = w;
        for (int o = 1; o < 32; o <<= 1) {
            unsigned n = __shfl_up_sync(~0u, vv, o);
            if (lane >= o) vv += n;
        }
        wsum[lane] = vv - w;
    }
    __syncthreads();
    unsigned excl = v - ps + wsum[wid];
    unsigned p0 = excl;
    unsigned p1 = excl + tots[2 * tid];
    g_bstart[2 * tid] = p0;     g_cursor[2 * tid] = p0;
    g_bstart[2 * tid + 1] = p1; g_cursor[2 * tid + 1] = p1;
    if (tid == 1023) g_bstart[2048] = p1 + tots[2047];
}

__global__ void __launch_bounds__(1024) sort_scatter(const float* __restrict__ coords) {
    int gi = blockIdx.x * 1024 + threadIdx.x;
    float v = coords[3 * gi];
    int b = (int)(v * 2048.f); if (b > 2047) b = 2047;
    unsigned pos = atomicAdd(&g_cursor[b], 1u);
    g_sort2[pos] = ((unsigned long long)__float_as_uint(v) << 32) | (unsigned)gi;
}

__global__ void __launch_bounds__(1024) sort_buckets() {
    __shared__ unsigned long long sb[32][128];
    int wid = threadIdx.x >> 5, lane = threadIdx.x & 31;
    int b = blockIdx.x * 32 + wid;
    unsigned s0 = g_bstart[b], s1 = g_bstart[b + 1];
    int n = (int)(s1 - s0);
    if (n <= 32) {
        // whole bucket in registers: rank via warp shuffles, no smem
        unsigned long long key = (lane < n) ? g_sort2[s0 + lane] : ~0ULL;
        int r = 0;
#pragma unroll
        for (int j = 0; j < 32; j++) {
            unsigned long long kj = __shfl_sync(~0u, key, j);
            r += (kj < key) ? 1 : 0;
        }
        if (lane < n) g_sort[s0 + (unsigned)r] = key;
    } else if (n <= 128) {
        for (int i = lane; i < n; i += 32) sb[wid][i] = g_sort2[s0 + i];
        __syncwarp();
        for (int i = lane; i < n; i += 32) {
            unsigned long long key = sb[wid][i];
            int r = 0;
            for (int j = 0; j < n; j++) r += (sb[wid][j] < key) ? 1 : 0;
            g_sort[s0 + (unsigned)r] = key;
        }
    } else {
        for (int i = lane; i < n; i += 32) {
            unsigned long long key = g_sort2[s0 + i];
            int r = 0;
            for (int j = 0; j < n; j++) r += (g_sort2[s0 + j] < key) ? 1 : 0;
            g_sort[s0 + (unsigned)r] = key;
        }
    }
}

// ---------------- A: LN1 -> xn bf16 (sorted token-major) + coords ----------------
__global__ void __launch_bounds__(256) ln1_kernel(
    const float* __restrict__ x, const float* __restrict__ coords,
    const float* __restrict__ g1, const float* __restrict__ be1) {
    int tid = threadIdx.x;
    int s = blockIdx.x * 256 + tid;
    int orig = (int)(g_sort[s] & 0xffffffffULL);

    float xv[32];
    const float4* xp = (const float4*)(x + orig * 32);
#pragma unroll
    for (int q8 = 0; q8 < 8; q8++) {
        float4 t = xp[q8];
        xv[4 * q8] = t.x; xv[4 * q8 + 1] = t.y; xv[4 * q8 + 2] = t.z; xv[4 * q8 + 3] = t.w;
    }
    float mu = 0.f;
#pragma unroll
    for (int d = 0; d < 32; d++) mu += xv[d];
    mu *= (1.f / 32.f);
    float var = 0.f;
#pragma unroll
    for (int d = 0; d < 32; d++) { float c = xv[d] - mu; var = fmaf(c, c, var); }
    var *= (1.f / 32.f);
    float inv = rsqrtf(var + 1e-5f);
#pragma unroll
    for (int d = 0; d < 32; d++) xv[d] = (xv[d] - mu) * inv * g1[d] + be1[d];

    unsigned* dst = g_xnb + (size_t)s * 16;
#pragma unroll
    for (int u = 0; u < 4; u++) {
        uint4 t;
        t.x = pack_bf16x2(xv[8 * u + 0], xv[8 * u + 1]);
        t.y = pack_bf16x2(xv[8 * u + 2], xv[8 * u + 3]);
        t.z = pack_bf16x2(xv[8 * u + 4], xv[8 * u + 5]);
        t.w = pack_bf16x2(xv[8 * u + 6], xv[8 * u + 7]);
        ((uint4*)dst)[u] = t;
    }
    g_p[2 * s]     = coords[3 * orig + 1];
    g_p[2 * s + 1] = coords[3 * orig + 2];
}

// ---------------- B: per (block, head): in-CTA QKV proj + attention (R11 exact) ----------------
// smem (u32): xn [0,5120) K [5120,10240) V [10240,15360) p [15360,15872) cj [15872,16128)
__global__ void __launch_bounds__(256, 2) attn_kernel() {
    extern __shared__ __align__(16) unsigned smem[];
    unsigned* xnsh = smem;
    unsigned* Ksh  = smem + 5120;
    unsigned* Vsh  = smem + 10240;
    float2*   psh2 = (float2*)(smem + 15360);
    float*    cjsh = (float*)(smem + 15872);

    int tid = threadIdx.x, wid = tid >> 5, lane = tid & 31;
    int bh = blockIdx.x;
    int b = bh >> 3, h = bh & 7;
    float w20L = g_w2[2 * h] * L2E, w21L = g_w2[2 * h + 1] * L2E;

    {
        const uint4* src = (const uint4*)(g_xnb + (size_t)(b * 256 + tid) * 16);
        unsigned* d = xnsh + tid * 20;
#pragma unroll
        for (int u = 0; u < 4; u++) {
            uint4 t = src[u];
            d[4 * u] = t.x; d[4 * u + 1] = t.y; d[4 * u + 2] = t.z; d[4 * u + 3] = t.w;
        }
        float2 pp = ((const float2*)(g_p + b * 512))[tid];
        psh2[tid] = pp;
        cjsh[tid] = fmaf(w20L * pp.x, pp.x, w21L * pp.y * pp.y);
    }
    __syncthreads();

    int r4 = lane >> 2, tig = lane & 3;
    int lrow = lane & 7, lmat = lane >> 3;
    int mi = wid * 32;
    int row0 = mi + r4;
    unsigned sK = smem_u32(Ksh), sV = smem_u32(Vsh);
    const float qsc = 0.17677669529663687f * L2E;

    unsigned af[2][2][4];
#pragma unroll
    for (int m = 0; m < 2; m++)
#pragma unroll
        for (int ks = 0; ks < 2; ks++) {
            int rw = row0 + m * 16;
            af[m][ks][0] = xnsh[rw * 20 + ks * 8 + tig];
            af[m][ks][1] = xnsh[(rw + 8) * 20 + ks * 8 + tig];
            af[m][ks][2] = xnsh[rw * 20 + ks * 8 + tig + 4];
            af[m][ks][3] = xnsh[(rw + 8) * 20 + ks * 8 + tig + 4];
        }

    unsigned qf[2][2][4];
#pragma unroll
    for (int n0i = 0; n0i < 4; n0i++) {
        int wrow = (h * 32 + n0i * 8 + (lane >> 2)) * 16 + tig;
        {
            unsigned b00 = g_wqkvb[4096 + wrow], b01 = g_wqkvb[4096 + wrow + 4];
            unsigned b10 = g_wqkvb[4096 + wrow + 8], b11 = g_wqkvb[4096 + wrow + 12];
#pragma unroll
            for (int m = 0; m < 2; m++) {
                float acc[4] = {0.f, 0.f, 0.f, 0.f};
                mma_bf16(acc, af[m][0], b00, b01);
                mma_bf16(acc, af[m][1], b10, b11);
                int rw = row0 + m * 16;
                Ksh[rw * 20 + n0i * 4 + tig]       = pack_bf16x2(acc[0], acc[1]);
                Ksh[(rw + 8) * 20 + n0i * 4 + tig] = pack_bf16x2(acc[2], acc[3]);
            }
        }
        {
            unsigned b00 = g_wqkvb[8192 + wrow], b01 = g_wqkvb[8192 + wrow + 4];
            unsigned b10 = g_wqkvb[8192 + wrow + 8], b11 = g_wqkvb[8192 + wrow + 12];
#pragma unroll
            for (int m = 0; m < 2; m++) {
                float acc[4] = {0.f, 0.f, 0.f, 0.f};
                mma_bf16(acc, af[m][0], b00, b01);
                mma_bf16(acc, af[m][1], b10, b11);
                int rw = row0 + m * 16;
                Vsh[rw * 20 + n0i * 4 + tig]       = pack_bf16x2(acc[0], acc[1]);
                Vsh[(rw + 8) * 20 + n0i * 4 + tig] = pack_bf16x2(acc[2], acc[3]);
            }
        }
    }
    {
        float qacc[2][4][4];
#pragma unroll
        for (int n0i = 0; n0i < 4; n0i++) {
            int wrow = (h * 32 + n0i * 8 + (lane >> 2)) * 16 + tig;
            unsigned b00 = g_wqkvb[wrow], b01 = g_wqkvb[wrow + 4];
            unsigned b10 = g_wqkvb[wrow + 8], b11 = g_wqkvb[wrow + 12];
#pragma unroll
            for (int m = 0; m < 2; m++) {
#pragma unroll
                for (int e = 0; e < 4; e++) qacc[m][n0i][e] = 0.f;
                mma_bf16(qacc[m][n0i], af[m][0], b00, b01);
                mma_bf16(qacc[m][n0i], af[m][1], b10, b11);
            }
        }
#pragma unroll
        for (int m = 0; m < 2; m++)
#pragma unroll
            for (int ks = 0; ks < 2; ks++) {
                qf[m][ks][0] = pack_bf16x2(qacc[m][2 * ks][0] * qsc, qacc[m][2 * ks][1] * qsc);
                qf[m][ks][1] = pack_bf16x2(qacc[m][2 * ks][2] * qsc, qacc[m][2 * ks][3] * qsc);
                qf[m][ks][2] = pack_bf16x2(qacc[m][2 * ks + 1][0] * qsc, qacc[m][2 * ks + 1][1] * qsc);
                qf[m][ks][3] = pack_bf16x2(qacc[m][2 * ks + 1][2] * qsc, qacc[m][2 * ks + 1][3] * qsc);
            }
    }
    unsigned ax[2][4];
#pragma unroll
    for (int m = 0; m < 2; m++) {
        float2 pa = psh2[row0 + m * 16];
        float2 pb = psh2[row0 + m * 16 + 8];
        ax[m][0] = (tig == 0) ? pack_bf16x2(2.f * w20L * pa.x, 2.f * w21L * pa.y) : 0u;
        ax[m][1] = (tig == 0) ? pack_bf16x2(2.f * w20L * pb.x, 2.f * w21L * pb.y) : 0u;
        ax[m][2] = 0u; ax[m][3] = 0u;
    }
    __syncthreads();

    float oacc[2][4][4];
#pragma unroll
    for (int m = 0; m < 2; m++)
#pragma unroll
        for (int n = 0; n < 4; n++)
#pragma unroll
            for (int e = 0; e < 4; e++) oacc[m][n][e] = 0.f;
    float lsum[4] = {0.f, 0.f, 0.f, 0.f};

    for (int c = 0; c < 16; c++) {
        int j0 = c * 16;
        unsigned kr[2][4];
#pragma unroll
        for (int f = 0; f < 2; f++)
            ldm_x4(kr[f], sK + (((j0 + f * 8 + lrow) * 20 + lmat * 4) << 2));
        unsigned xb[2][2];
#pragma unroll
        for (int f = 0; f < 2; f++) {
            float2 pj = psh2[j0 + f * 8 + r4];
            xb[f][0] = (tig == 0) ? pack_bf16x2(pj.x, pj.y) : 0u;
            xb[f][1] = 0u;
        }
        float sa[2][2][4];
#pragma unroll
        for (int m = 0; m < 2; m++)
#pragma unroll
            for (int f = 0; f < 2; f++) {
#pragma unroll
                for (int e = 0; e < 4; e++) sa[m][f][e] = 0.f;
                mma_bf16(sa[m][f], qf[m][0], kr[f][0], kr[f][1]);
                mma_bf16(sa[m][f], qf[m][1], kr[f][2], kr[f][3]);
                mma_bf16(sa[m][f], ax[m], xb[f][0], xb[f][1]);
            }
        unsigned pA[2][4];
#pragma unroll
        for (int m = 0; m < 2; m++)
#pragma unroll
            for (int f = 0; f < 2; f++) {
                int jj = j0 + f * 8 + tig * 2;
                float cj0 = cjsh[jj], cj1 = cjsh[jj + 1];
                float e0 = ex2f(sa[m][f][0] - cj0);
                float e1 = ex2f(sa[m][f][1] - cj1);
                float e2 = ex2f(sa[m][f][2] - cj0);
                float e3 = ex2f(sa[m][f][3] - cj1);
                lsum[m * 2 + 0] += e0 + e1;
                lsum[m * 2 + 1] += e2 + e3;
                pA[m][f * 2 + 0] = pack_bf16x2(e0, e1);
                pA[m][f * 2 + 1] = pack_bf16x2(e2, e3);
            }
        unsigned vr[2][4];
#pragma unroll
        for (int g2i = 0; g2i < 2; g2i++)
            ldm_x4t(vr[g2i], sV + (((j0 + (lmat & 1) * 8 + lrow) * 20
                                    + (2 * g2i + (lmat >> 1)) * 4) << 2));
#pragma unroll
        for (int n2 = 0; n2 < 4; n2++) {
            unsigned vb0 = vr[n2 >> 1][(n2 & 1) * 2];
            unsigned vb1 = vr[n2 >> 1][(n2 & 1) * 2 + 1];
            mma_bf16(oacc[0][n2], pA[0], vb0, vb1);
            mma_bf16(oacc[1][n2], pA[1], vb0, vb1);
        }
    }

#pragma unroll
    for (int r = 0; r < 4; r++) {
        lsum[r] += __shfl_xor_sync(0xffffffffu, lsum[r], 1);
        lsum[r] += __shfl_xor_sync(0xffffffffu, lsum[r], 2);
    }
    float linv[4];
#pragma unroll
    for (int r = 0; r < 4; r++) linv[r] = 1.f / lsum[r];

    unsigned* og = g_attb + (size_t)b * 256 * 128;
#pragma unroll
    for (int m = 0; m < 2; m++) {
        int row = mi + m * 16 + r4;
#pragma unroll
        for (int n2 = 0; n2 < 4; n2++) {
            unsigned v0 = pack_bf16x2(oacc[m][n2][0] * linv[m * 2],
                                      oacc[m][n2][1] * linv[m * 2]);
            unsigned v1 = pack_bf16x2(oacc[m][n2][2] * linv[m * 2 + 1],
                                      oacc[m][n2][3] * linv[m * 2 + 1]);
            og[row * 128 + h * 16 + n2 * 4 + tig] = v0;
            og[(row + 8) * 128 + h * 16 + n2 * 4 + tig] = v1;
        }
    }
}

// ---------------- C: HMMA out-proj + LN2 + HMMA FFN + residual + scatter ----------------
// dynamic smem (u32): ybuf [0, 8448) f32 pitch 33 (woutu bf16 overlays start)
//                     lnsh [8448, 13568) bf16x2 pitch 20
__global__ void __launch_bounds__(256, 2) epi_kernel(
    const float* __restrict__ x, const float* __restrict__ bout,
    const float* __restrict__ g2, const float* __restrict__ be2,
    const float* __restrict__ fb1, const float* __restrict__ fb2,
    float* __restrict__ out) {
    extern __shared__ __align__(16) unsigned esmem[];
    float* ybuf = (float*)esmem;
    unsigned* lnsh = esmem + 8448;
    unsigned* woutu = esmem;          // [32][132] bf16x2, overlays ybuf

    int tid = threadIdx.x, wid = tid >> 5, lane = tid & 31;
    int b = blockIdx.x;

    {
        int idx = tid;
#pragma unroll
        for (int u = 0; u < 16; u++) {
            int o = idx >> 7, c = idx & 127;
            woutu[o * 132 + c] = g_woutb[idx];
            idx += 256;
        }
    }
    __syncthreads();

    int r4 = lane >> 2, tig = lane & 3;
    int mi = wid * 32;
    unsigned wbase = smem_u32(woutu);
    int lrow = lane & 7, lmat = lane >> 3;
    const unsigned* ag = g_attb + (size_t)b * 256 * 128;

    // ---- out-proj: y = att @ wout^T ----
    float yacc[2][4][4];
#pragma unroll
    for (int m = 0; m < 2; m++)
#pragma unroll
        for (int n = 0; n < 4; n++)
#pragma unroll
            for (int e = 0; e < 4; e++) yacc[m][n][e] = 0.f;

    for (int sp = 0; sp < 8; sp++) {
        unsigned br[4][4];
#pragma unroll
        for (int n0i = 0; n0i < 4; n0i++)
            ldm_x4(br[n0i], wbase + (((n0i * 8 + lrow) * 132 + (4 * sp + lmat) * 4) << 2));
        unsigned af0[2][4], af1[2][4];
#pragma unroll
        for (int m = 0; m < 2; m++) {
            int rw = mi + m * 16 + r4;
            const unsigned* arow = ag + rw * 128 + sp * 16 + tig;
            const unsigned* arow8 = ag + (rw + 8) * 128 + sp * 16 + tig;
            af0[m][0] = arow[0];  af0[m][1] = arow8[0];
            af0[m][2] = arow[4];  af0[m][3] = arow8[4];
            af1[m][0] = arow[8];  af1[m][1] = arow8[8];
            af1[m][2] = arow[12]; af1[m][3] = arow8[12];
        }
#pragma unroll
        for (int m = 0; m < 2; m++)
#pragma unroll
            for (int n0i = 0; n0i < 4; n0i++) {
                mma_bf16(yacc[m][n0i], af0[m], br[n0i][0], br[n0i][1]);
                mma_bf16(yacc[m][n0i], af1[m], br[n0i][2], br[n0i][3]);
            }
    }
    __syncthreads();   // done reading woutu; reuse as ybuf
#pragma unroll
    for (int m = 0; m < 2; m++) {
        int rw = mi + m * 16 + r4;
#pragma unroll
        for (int n0i = 0; n0i < 4; n0i++) {
            int col = n0i * 8 + 2 * tig;
            ybuf[rw * 33 + col]           = yacc[m][n0i][0];
            ybuf[rw * 33 + col + 1]       = yacc[m][n0i][1];
            ybuf[(rw + 8) * 33 + col]     = yacc[m][n0i][2];
            ybuf[(rw + 8) * 33 + col + 1] = yacc[m][n0i][3];
        }
    }
    __syncthreads();

    // ---- per-token: residual + LN2 -> lnsh (bf16) ; keep x2 in regs ----
    int s = b * 256 + tid;
    int orig = (int)(g_sort[s] & 0xffffffffULL);
    float x2[32];
    const float4* xp = (const float4*)(x + orig * 32);
#pragma unroll
    for (int q8 = 0; q8 < 8; q8++) {
        float4 t = xp[q8];
        x2[4 * q8]     = t.x + ybuf[tid * 33 + 4 * q8]     + bout[4 * q8];
        x2[4 * q8 + 1] = t.y + ybuf[tid * 33 + 4 * q8 + 1] + bout[4 * q8 + 1];
        x2[4 * q8 + 2] = t.z + ybuf[tid * 33 + 4 * q8 + 2] + bout[4 * q8 + 2];
        x2[4 * q8 + 3] = t.w + ybuf[tid * 33 + 4 * q8 + 3] + bout[4 * q8 + 3];
    }
    float mu2 = 0.f;
#pragma unroll
    for (int d = 0; d < 32; d++) mu2 += x2[d];
    mu2 *= (1.f / 32.f);
    float var2 = 0.f;
#pragma unroll
    for (int d = 0; d < 32; d++) { float c = x2[d] - mu2; var2 = fmaf(c, c, var2); }
    var2 *= (1.f / 32.f);
    float inv2 = rsqrtf(var2 + 1e-5f);
#pragma unroll
    for (int c = 0; c < 16; c++) {
        float l0 = (x2[2 * c]     - mu2) * inv2 * g2[2 * c]     + be2[2 * c];
        float l1 = (x2[2 * c + 1] - mu2) * inv2 * g2[2 * c + 1] + be2[2 * c + 1];
        lnsh[tid * 20 + c] = pack_bf16x2(l0, l1);
    }
    __syncthreads();

    // ---- FFN on tensor cores ----
    unsigned la[2][2][4];
#pragma unroll
    for (int m = 0; m < 2; m++)
#pragma unroll
        for (int ks = 0; ks < 2; ks++) {
            int rw = mi + r4 + m * 16;
            la[m][ks][0] = lnsh[rw * 20 + ks * 8 + tig];
            la[m][ks][1] = lnsh[(rw + 8) * 20 + ks * 8 + tig];
            la[m][ks][2] = lnsh[rw * 20 + ks * 8 + tig + 4];
            la[m][ks][3] = lnsh[(rw + 8) * 20 + ks * 8 + tig + 4];
        }

    unsigned hA[2][2][4];
    {
        float hacc[2][4][4];
#pragma unroll
        for (int n0i = 0; n0i < 4; n0i++) {
            int wrow = (n0i * 8 + r4) * 16 + tig;
            unsigned b00 = g_wffb[wrow], b01 = g_wffb[wrow + 4];
            unsigned b10 = g_wffb[wrow + 8], b11 = g_wffb[wrow + 12];
#pragma unroll
            for (int m = 0; m < 2; m++) {
#pragma unroll
                for (int e = 0; e < 4; e++) hacc[m][n0i][e] = 0.f;
                mma_bf16(hacc[m][n0i], la[m][0], b00, b01);
                mma_bf16(hacc[m][n0i], la[m][1], b10, b11);
            }
        }
#pragma unroll
        for (int n0i = 0; n0i < 4; n0i++) {
            int c0 = n0i * 8 + 2 * tig;
            float f0 = fb1[c0], f1 = fb1[c0 + 1];
#pragma unroll
            for (int m = 0; m < 2; m++) {
                hacc[m][n0i][0] = fmaxf(hacc[m][n0i][0] + f0, 0.f);
                hacc[m][n0i][1] = fmaxf(hacc[m][n0i][1] + f1, 0.f);
                hacc[m][n0i][2] = fmaxf(hacc[m][n0i][2] + f0, 0.f);
                hacc[m][n0i][3] = fmaxf(hacc[m][n0i][3] + f1, 0.f);
            }
        }
#pragma unroll
        for (int m = 0; m < 2; m++)
#pragma unroll
            for (int ks = 0; ks < 2; ks++) {
                hA[m][ks][0] = pack_bf16x2(hacc[m][2 * ks][0], hacc[m][2 * ks][1]);
                hA[m][ks][1] = pack_bf16x2(hacc[m][2 * ks][2], hacc[m][2 * ks][3]);
                hA[m][ks][2] = pack_bf16x2(hacc[m][2 * ks + 1][0], hacc[m][2 * ks + 1][1]);
                hA[m][ks][3] = pack_bf16x2(hacc[m][2 * ks + 1][2], hacc[m][2 * ks + 1][3]);
            }
    }

    float facc[2][4][4];
#pragma unroll
    for (int n0i = 0; n0i < 4; n0i++) {
        int wrow = 512 + (n0i * 8 + r4) * 16 + tig;
        unsigned b00 = g_wffb[wrow], b01 = g_wffb[wrow + 4];
        unsigned b10 = g_wffb[wrow + 8], b11 = g_wffb[wrow + 12];
#pragma unroll
        for (int m = 0; m < 2; m++) {
#pragma unroll
            for (int e = 0; e < 4; e++) facc[m][n0i][e] = 0.f;
            mma_bf16(facc[m][n0i], hA[m][0], b00, b01);
            mma_bf16(facc[m][n0i], hA[m][1], b10, b11);
        }
    }
#pragma unroll
    for (int m = 0; m < 2; m++) {
        int rw = mi + m * 16 + r4;
#pragma unroll
        for (int n0i = 0; n0i < 4; n0i++) {
            int col = n0i * 8 + 2 * tig;
            ybuf[rw * 33 + col]           = facc[m][n0i][0];
            ybuf[rw * 33 + col + 1]       = facc[m][n0i][1];
            ybuf[(rw + 8) * 33 + col]     = facc[m][n0i][2];
            ybuf[(rw + 8) * 33 + col + 1] = facc[m][n0i][3];
        }
    }
    __syncthreads();

    float4* op = (float4*)(out + orig * 32);
#pragma unroll
    for (int q8 = 0; q8 < 8; q8++) {
        float4 t;
        t.x = x2[4 * q8]     + ybuf[tid * 33 + 4 * q8]     + fb2[4 * q8];
        t.y = x2[4 * q8 + 1] + ybuf[tid * 33 + 4 * q8 + 1] + fb2[4 * q8 + 1];
        t.z = x2[4 * q8 + 2] + ybuf[tid * 33 + 4 * q8 + 2] + fb2[4 * q8 + 2];
        t.w = x2[4 * q8 + 3] + ybuf[tid * 33 + 4 * q8 + 3] + fb2[4 * q8 + 3];
        op[q8] = t;
    }
}

// ---------------- host launcher ----------------
#define ATTN_SMEM (16128 * 4)
#define EPI_SMEM (13568 * 4)

extern "C" void kernel_launch(void* const* d_in, const int* in_sizes, int n_in,
                              void* d_out, int out_size) {
    const float* x      = (const float*)d_in[0];
    const float* coords = (const float*)d_in[1];
    const float* wq     = (const float*)d_in[2];
    const float* wk     = (const float*)d_in[3];
    const float* wv     = (const float*)d_in[4];
    const float* wrpe   = (const float*)d_in[5];
    const float* wout   = (const float*)d_in[6];
    const float* bout   = (const float*)d_in[7];
    const float* g1     = (const float*)d_in[8];
    const float* be1    = (const float*)d_in[9];
    const float* g2     = (const float*)d_in[10];
    const float* be2    = (const float*)d_in[11];
    const float* fw1    = (const float*)d_in[12];
    const float* fb1    = (const float*)d_in[13];
    const float* fw2    = (const float*)d_in[14];
    const float* fb2    = (const float*)d_in[15];
    float* out = (float*)d_out;

    cudaFuncSetAttribute(attn_kernel, cudaFuncAttributeMaxDynamicSharedMemorySize, ATTN_SMEM);
    cudaFuncSetAttribute(epi_kernel, cudaFuncAttributeMaxDynamicSharedMemorySize, EPI_SMEM);

    sort_hist<<<64, 1024>>>(coords);
    sort_prefix_prep<<<1, 1024>>>(wq, wk, wv, wout, wrpe, fw1, fw2);
    sort_scatter<<<64, 1024>>>(coords);
    sort_buckets<<<64, 1024>>>();
    ln1_kernel<<<NBLK, 256>>>(x, coords, g1, be1);
    attn_kernel<<<NBLK * NH, 256, ATTN_SMEM>>>();
    epi_kernel<<<NBLK, 256, EPI_SMEM>>>(x, bout, g2, be2, fb1, fb2, out);
}

// round 16
// speedup vs baseline: 1.0059x; 1.0059x over previous
#include <cuda_runtime.h>
#include <cuda_bf16.h>
#include <math.h>
#include <stdint.h>

#define N_TOK 65536
#define DD 32
#define NH 8
#define NBLK 256
#define L2E 1.4426950408889634f

// ---------------- device scratch ----------------
__device__ unsigned long long g_sort[N_TOK];               // (key<<32)|idx, sorted
__device__ unsigned long long g_sort2[N_TOK];              // bucket-grouped
__device__ unsigned g_histc[64 * 2048];
__device__ unsigned g_bstart[2049];
__device__ unsigned g_cursor[2048];
__device__ float g_w2[16];
__device__ __align__(16) unsigned g_wqkvb[3 * 256 * 16];   // bf16x2 [w][o][16]
__device__ __align__(16) unsigned g_woutb[32 * 128];       // bf16x2 [o][128]
__device__ __align__(16) unsigned g_wffb[1024];            // bf16x2 ffn w1 [0,512) w2 [512,1024)
__device__ __align__(16) unsigned g_xnb[N_TOK * 16];       // bf16x2 xn, sorted token-major
__device__ __align__(16) unsigned g_attb[N_TOK * 128];     // bf16x2 [b][i][128] token-major
__device__ float g_p[N_TOK * 2];

// ---------------- helpers ----------------
__device__ __forceinline__ unsigned pack_bf16x2(float lo, float hi) {
    unsigned r;
    asm("cvt.rn.bf16x2.f32 %0, %1, %2;" : "=r"(r) : "f"(hi), "f"(lo));
    return r;
}
__device__ __forceinline__ unsigned smem_u32(const void* p) {
    unsigned a;
    asm("{ .reg .u64 t; cvta.to.shared.u64 t, %1; cvt.u32.u64 %0, t; }" : "=r"(a) : "l"(p));
    return a;
}
__device__ __forceinline__ float ex2f(float x) {
    float r; asm("ex2.approx.f32 %0, %1;" : "=f"(r) : "f"(x)); return r;
}
__device__ __forceinline__ void mma_bf16(float c[4], const unsigned a[4],
                                         unsigned b0, unsigned b1) {
    asm volatile("mma.sync.aligned.m16n8k16.row.col.f32.bf16.bf16.f32 "
                 "{%0,%1,%2,%3}, {%4,%5,%6,%7}, {%8,%9}, {%0,%1,%2,%3};"
                 : "+f"(c[0]), "+f"(c[1]), "+f"(c[2]), "+f"(c[3])
                 : "r"(a[0]), "r"(a[1]), "r"(a[2]), "r"(a[3]), "r"(b0), "r"(b1));
}
__device__ __forceinline__ void ldm_x4(unsigned r[4], unsigned addr) {
    asm volatile("ldmatrix.sync.aligned.m8n8.x4.shared.b16 {%0,%1,%2,%3}, [%4];"
                 : "=r"(r[0]), "=r"(r[1]), "=r"(r[2]), "=r"(r[3]) : "r"(addr));
}
__device__ __forceinline__ void ldm_x4t(unsigned r[4], unsigned addr) {
    asm volatile("ldmatrix.sync.aligned.m8n8.x4.trans.shared.b16 {%0,%1,%2,%3}, [%4];"
                 : "=r"(r[0]), "=r"(r[1]), "=r"(r[2]), "=r"(r[3]) : "r"(addr));
}

// ---------------- bucket sort ----------------
__global__ void __launch_bounds__(1024) sort_hist(const float* __restrict__ coords) {
    __shared__ unsigned hist[2048];
    int tid = threadIdx.x;
    hist[tid] = 0; hist[tid + 1024] = 0;
    __syncthreads();
    int gi = blockIdx.x * 1024 + tid;
    float v = coords[3 * gi];
    int b = (int)(v * 2048.f); if (b > 2047) b = 2047;
    atomicAdd(&hist[b], 1u);
    __syncthreads();
    g_histc[blockIdx.x * 2048 + tid] = hist[tid];
    g_histc[blockIdx.x * 2048 + tid + 1024] = hist[tid + 1024];
}

__global__ void __launch_bounds__(1024) sort_prefix_prep(
    const float* __restrict__ wq, const float* __restrict__ wk,
    const float* __restrict__ wv, const float* __restrict__ wout,
    const float* __restrict__ wrpe,
    const float* __restrict__ fw1, const float* __restrict__ fw2) {
    __shared__ unsigned tots[2048];
    __shared__ unsigned wsum[32];
    int tid = threadIdx.x;
    int lane = tid & 31, wid = tid >> 5;

    for (int gid = tid; gid < 16384; gid += 1024) {
        if (gid < 12288) {
            const float* src = (gid < 4096) ? wq : (gid < 8192) ? wk : wv;
            int r = gid & 4095; int o = r >> 4, c = r & 15;
            g_wqkvb[gid] = pack_bf16x2(src[o * 32 + 2 * c], src[o * 32 + 2 * c + 1]);
        } else {
            int r = gid - 12288; int o = r >> 7, c = r & 127;
            g_woutb[r] = pack_bf16x2(wout[o * 256 + 2 * c], wout[o * 256 + 2 * c + 1]);
        }
    }
    if (tid < 1024) {
        const float* srcf = (tid < 512) ? fw1 : fw2;
        int r = tid & 511;
        int o = r >> 4, c = r & 15;
        g_wffb[tid] = pack_bf16x2(srcf[o * 32 + 2 * c], srcf[o * 32 + 2 * c + 1]);
    }
    if (tid < 16) {
        int h = tid >> 1, c = tid & 1;
        float acc = 0.f;
        for (int d = 0; d < 32; d++)
            for (int w = 0; w < 8; w++) {
                float v = wrpe[(h * 32 + d) * 16 + c * 8 + w];
                acc += v * v;
            }
        g_w2[tid] = acc * (1.f / 256.f);
    }

    for (int b = tid; b < 2048; b += 1024) {
        unsigned t = 0;
        for (int c = 0; c < 64; c++) t += g_histc[c * 2048 + b];
        tots[b] = t;
    }
    __syncthreads();
    unsigned ps = tots[2 * tid] + tots[2 * tid + 1];
    unsigned v = ps;
    for (int o = 1; o < 32; o <<= 1) {
        unsigned n = __shfl_up_sync(~0u, v, o);
        if (lane >= o) v += n;
    }
    if (lane == 31) wsum[wid] = v;
    __syncthreads();
    if (wid == 0) {
        unsigned w = wsum[lane];
        unsigned vv = w;
        for (int o = 1; o < 32; o <<= 1) {
            unsigned n = __shfl_up_sync(~0u, vv, o);
            if (lane >= o) vv += n;
        }
        wsum[lane] = vv - w;
    }
    __syncthreads();
    unsigned excl = v - ps + wsum[wid];
    unsigned p0 = excl;
    unsigned p1 = excl + tots[2 * tid];
    g_bstart[2 * tid] = p0;     g_cursor[2 * tid] = p0;
    g_bstart[2 * tid + 1] = p1; g_cursor[2 * tid + 1] = p1;
    if (tid == 1023) g_bstart[2048] = p1 + tots[2047];
}

__global__ void __launch_bounds__(256) sort_scatter(const float* __restrict__ coords) {
    int gi = blockIdx.x * 256 + threadIdx.x;
    float v = coords[3 * gi];
    int b = (int)(v * 2048.f); if (b > 2047) b = 2047;
    unsigned pos = atomicAdd(&g_cursor[b], 1u);
    g_sort2[pos] = ((unsigned long long)__float_as_uint(v) << 32) | (unsigned)gi;
}

__global__ void __launch_bounds__(256) sort_buckets() {
    __shared__ unsigned long long sb[8][128];
    int wid = threadIdx.x >> 5, lane = threadIdx.x & 31;
    int b = blockIdx.x * 8 + wid;
    unsigned s0 = g_bstart[b], s1 = g_bstart[b + 1];
    int n = (int)(s1 - s0);
    if (n <= 32) {
        unsigned long long key = (lane < n) ? g_sort2[s0 + lane] : ~0ULL;
        int r = 0;
#pragma unroll
        for (int j = 0; j < 32; j++) {
            unsigned long long kj = __shfl_sync(~0u, key, j);
            r += (kj < key) ? 1 : 0;
        }
        if (lane < n) g_sort[s0 + (unsigned)r] = key;
    } else if (n <= 128) {
        for (int i = lane; i < n; i += 32) sb[wid][i] = g_sort2[s0 + i];
        __syncwarp();
        for (int i = lane; i < n; i += 32) {
            unsigned long long key = sb[wid][i];
            int r = 0;
            for (int j = 0; j < n; j++) r += (sb[wid][j] < key) ? 1 : 0;
            g_sort[s0 + (unsigned)r] = key;
        }
    } else {
        for (int i = lane; i < n; i += 32) {
            unsigned long long key = g_sort2[s0 + i];
            int r = 0;
            for (int j = 0; j < n; j++) r += (g_sort2[s0 + j] < key) ? 1 : 0;
            g_sort[s0 + (unsigned)r] = key;
        }
    }
}

// ---------------- A: LN1 -> xn bf16 (sorted token-major) + coords ----------------
__global__ void __launch_bounds__(256) ln1_kernel(
    const float* __restrict__ x, const float* __restrict__ coords,
    const float* __restrict__ g1, const float* __restrict__ be1) {
    int tid = threadIdx.x;
    int s = blockIdx.x * 256 + tid;
    int orig = (int)(g_sort[s] & 0xffffffffULL);

    float xv[32];
    const float4* xp = (const float4*)(x + orig * 32);
#pragma unroll
    for (int q8 = 0; q8 < 8; q8++) {
        float4 t = xp[q8];
        xv[4 * q8] = t.x; xv[4 * q8 + 1] = t.y; xv[4 * q8 + 2] = t.z; xv[4 * q8 + 3] = t.w;
    }
    float mu = 0.f;
#pragma unroll
    for (int d = 0; d < 32; d++) mu += xv[d];
    mu *= (1.f / 32.f);
    float var = 0.f;
#pragma unroll
    for (int d = 0; d < 32; d++) { float c = xv[d] - mu; var = fmaf(c, c, var); }
    var *= (1.f / 32.f);
    float inv = rsqrtf(var + 1e-5f);
#pragma unroll
    for (int d = 0; d < 32; d++) xv[d] = (xv[d] - mu) * inv * g1[d] + be1[d];

    unsigned* dst = g_xnb + (size_t)s * 16;
#pragma unroll
    for (int u = 0; u < 4; u++) {
        uint4 t;
        t.x = pack_bf16x2(xv[8 * u + 0], xv[8 * u + 1]);
        t.y = pack_bf16x2(xv[8 * u + 2], xv[8 * u + 3]);
        t.z = pack_bf16x2(xv[8 * u + 4], xv[8 * u + 5]);
        t.w = pack_bf16x2(xv[8 * u + 6], xv[8 * u + 7]);
        ((uint4*)dst)[u] = t;
    }
    g_p[2 * s]     = coords[3 * orig + 1];
    g_p[2 * s + 1] = coords[3 * orig + 2];
}

// ---------------- B: per (block, head): in-CTA QKV proj + attention (R11 exact) ----------------
// smem (u32): xn [0,5120) K [5120,10240) V [10240,15360) p [15360,15872) cj [15872,16128)
__global__ void __launch_bounds__(256, 2) attn_kernel() {
    extern __shared__ __align__(16) unsigned smem[];
    unsigned* xnsh = smem;
    unsigned* Ksh  = smem + 5120;
    unsigned* Vsh  = smem + 10240;
    float2*   psh2 = (float2*)(smem + 15360);
    float*    cjsh = (float*)(smem + 15872);

    int tid = threadIdx.x, wid = tid >> 5, lane = tid & 31;
    int bh = blockIdx.x;
    int b = bh >> 3, h = bh & 7;
    float w20L = g_w2[2 * h] * L2E, w21L = g_w2[2 * h + 1] * L2E;

    {
        const uint4* src = (const uint4*)(g_xnb + (size_t)(b * 256 + tid) * 16);
        unsigned* d = xnsh + tid * 20;
#pragma unroll
        for (int u = 0; u < 4; u++) {
            uint4 t = src[u];
            d[4 * u] = t.x; d[4 * u + 1] = t.y; d[4 * u + 2] = t.z; d[4 * u + 3] = t.w;
        }
        float2 pp = ((const float2*)(g_p + b * 512))[tid];
        psh2[tid] = pp;
        cjsh[tid] = fmaf(w20L * pp.x, pp.x, w21L * pp.y * pp.y);
    }
    __syncthreads();

    int r4 = lane >> 2, tig = lane & 3;
    int lrow = lane & 7, lmat = lane >> 3;
    int mi = wid * 32;
    int row0 = mi + r4;
    unsigned sK = smem_u32(Ksh), sV = smem_u32(Vsh);
    const float qsc = 0.17677669529663687f * L2E;

    unsigned af[2][2][4];
#pragma unroll
    for (int m = 0; m < 2; m++)
#pragma unroll
        for (int ks = 0; ks < 2; ks++) {
            int rw = row0 + m * 16;
            af[m][ks][0] = xnsh[rw * 20 + ks * 8 + tig];
            af[m][ks][1] = xnsh[(rw + 8) * 20 + ks * 8 + tig];
            af[m][ks][2] = xnsh[rw * 20 + ks * 8 + tig + 4];
            af[m][ks][3] = xnsh[(rw + 8) * 20 + ks * 8 + tig + 4];
        }

    unsigned qf[2][2][4];
#pragma unroll
    for (int n0i = 0; n0i < 4; n0i++) {
        int wrow = (h * 32 + n0i * 8 + (lane >> 2)) * 16 + tig;
        {
            unsigned b00 = g_wqkvb[4096 + wrow], b01 = g_wqkvb[4096 + wrow + 4];
            unsigned b10 = g_wqkvb[4096 + wrow + 8], b11 = g_wqkvb[4096 + wrow + 12];
#pragma unroll
            for (int m = 0; m < 2; m++) {
                float acc[4] = {0.f, 0.f, 0.f, 0.f};
                mma_bf16(acc, af[m][0], b00, b01);
                mma_bf16(acc, af[m][1], b10, b11);
                int rw = row0 + m * 16;
                Ksh[rw * 20 + n0i * 4 + tig]       = pack_bf16x2(acc[0], acc[1]);
                Ksh[(rw + 8) * 20 + n0i * 4 + tig] = pack_bf16x2(acc[2], acc[3]);
            }
        }
        {
            unsigned b00 = g_wqkvb[8192 + wrow], b01 = g_wqkvb[8192 + wrow + 4];
            unsigned b10 = g_wqkvb[8192 + wrow + 8], b11 = g_wqkvb[8192 + wrow + 12];
#pragma unroll
            for (int m = 0; m < 2; m++) {
                float acc[4] = {0.f, 0.f, 0.f, 0.f};
                mma_bf16(acc, af[m][0], b00, b01);
                mma_bf16(acc, af[m][1], b10, b11);
                int rw = row0 + m * 16;
                Vsh[rw * 20 + n0i * 4 + tig]       = pack_bf16x2(acc[0], acc[1]);
                Vsh[(rw + 8) * 20 + n0i * 4 + tig] = pack_bf16x2(acc[2], acc[3]);
            }
        }
    }
    {
        float qacc[2][4][4];
#pragma unroll
        for (int n0i = 0; n0i < 4; n0i++) {
            int wrow = (h * 32 + n0i * 8 + (lane >> 2)) * 16 + tig;
            unsigned b00 = g_wqkvb[wrow], b01 = g_wqkvb[wrow + 4];
            unsigned b10 = g_wqkvb[wrow + 8], b11 = g_wqkvb[wrow + 12];
#pragma unroll
            for (int m = 0; m < 2; m++) {
#pragma unroll
                for (int e = 0; e < 4; e++) qacc[m][n0i][e] = 0.f;
                mma_bf16(qacc[m][n0i], af[m][0], b00, b01);
                mma_bf16(qacc[m][n0i], af[m][1], b10, b11);
            }
        }
#pragma unroll
        for (int m = 0; m < 2; m++)
#pragma unroll
            for (int ks = 0; ks < 2; ks++) {
                qf[m][ks][0] = pack_bf16x2(qacc[m][2 * ks][0] * qsc, qacc[m][2 * ks][1] * qsc);
                qf[m][ks][1] = pack_bf16x2(qacc[m][2 * ks][2] * qsc, qacc[m][2 * ks][3] * qsc);
                qf[m][ks][2] = pack_bf16x2(qacc[m][2 * ks + 1][0] * qsc, qacc[m][2 * ks + 1][1] * qsc);
                qf[m][ks][3] = pack_bf16x2(qacc[m][2 * ks + 1][2] * qsc, qacc[m][2 * ks + 1][3] * qsc);
            }
    }
    unsigned ax[2][4];
#pragma unroll
    for (int m = 0; m < 2; m++) {
        float2 pa = psh2[row0 + m * 16];
        float2 pb = psh2[row0 + m * 16 + 8];
        ax[m][0] = (tig == 0) ? pack_bf16x2(2.f * w20L * pa.x, 2.f * w21L * pa.y) : 0u;
        ax[m][1] = (tig == 0) ? pack_bf16x2(2.f * w20L * pb.x, 2.f * w21L * pb.y) : 0u;
        ax[m][2] = 0u; ax[m][3] = 0u;
    }
    __syncthreads();

    float oacc[2][4][4];
#pragma unroll
    for (int m = 0; m < 2; m++)
#pragma unroll
        for (int n = 0; n < 4; n++)
#pragma unroll
            for (int e = 0; e < 4; e++) oacc[m][n][e] = 0.f;
    float lsum[4] = {0.f, 0.f, 0.f, 0.f};

    for (int c = 0; c < 16; c++) {
        int j0 = c * 16;
        unsigned kr[2][4];
#pragma unroll
        for (int f = 0; f < 2; f++)
            ldm_x4(kr[f], sK + (((j0 + f * 8 + lrow) * 20 + lmat * 4) << 2));
        unsigned xb[2][2];
#pragma unroll
        for (int f = 0; f < 2; f++) {
            float2 pj = psh2[j0 + f * 8 + r4];
            xb[f][0] = (tig == 0) ? pack_bf16x2(pj.x, pj.y) : 0u;
            xb[f][1] = 0u;
        }
        float sa[2][2][4];
#pragma unroll
        for (int m = 0; m < 2; m++)
#pragma unroll
            for (int f = 0; f < 2; f++) {
#pragma unroll
                for (int e = 0; e < 4; e++) sa[m][f][e] = 0.f;
                mma_bf16(sa[m][f], qf[m][0], kr[f][0], kr[f][1]);
                mma_bf16(sa[m][f], qf[m][1], kr[f][2], kr[f][3]);
                mma_bf16(sa[m][f], ax[m], xb[f][0], xb[f][1]);
            }
        unsigned pA[2][4];
#pragma unroll
        for (int m = 0; m < 2; m++)
#pragma unroll
            for (int f = 0; f < 2; f++) {
                int jj = j0 + f * 8 + tig * 2;
                float cj0 = cjsh[jj], cj1 = cjsh[jj + 1];
                float e0 = ex2f(sa[m][f][0] - cj0);
                float e1 = ex2f(sa[m][f][1] - cj1);
                float e2 = ex2f(sa[m][f][2] - cj0);
                float e3 = ex2f(sa[m][f][3] - cj1);
                lsum[m * 2 + 0] += e0 + e1;
                lsum[m * 2 + 1] += e2 + e3;
                pA[m][f * 2 + 0] = pack_bf16x2(e0, e1);
                pA[m][f * 2 + 1] = pack_bf16x2(e2, e3);
            }
        unsigned vr[2][4];
#pragma unroll
        for (int g2i = 0; g2i < 2; g2i++)
            ldm_x4t(vr[g2i], sV + (((j0 + (lmat & 1) * 8 + lrow) * 20
                                    + (2 * g2i + (lmat >> 1)) * 4) << 2));
#pragma unroll
        for (int n2 = 0; n2 < 4; n2++) {
            unsigned vb0 = vr[n2 >> 1][(n2 & 1) * 2];
            unsigned vb1 = vr[n2 >> 1][(n2 & 1) * 2 + 1];
            mma_bf16(oacc[0][n2], pA[0], vb0, vb1);
            mma_bf16(oacc[1][n2], pA[1], vb0, vb1);
        }
    }

#pragma unroll
    for (int r = 0; r < 4; r++) {
        lsum[r] += __shfl_xor_sync(0xffffffffu, lsum[r], 1);
        lsum[r] += __shfl_xor_sync(0xffffffffu, lsum[r], 2);
    }
    float linv[4];
#pragma unroll
    for (int r = 0; r < 4; r++) linv[r] = 1.f / lsum[r];

    unsigned* og = g_attb + (size_t)b * 256 * 128;
#pragma unroll
    for (int m = 0; m < 2; m++) {
        int row = mi + m * 16 + r4;
#pragma unroll
        for (int n2 = 0; n2 < 4; n2++) {
            unsigned v0 = pack_bf16x2(oacc[m][n2][0] * linv[m * 2],
                                      oacc[m][n2][1] * linv[m * 2]);
            unsigned v1 = pack_bf16x2(oacc[m][n2][2] * linv[m * 2 + 1],
                                      oacc[m][n2][3] * linv[m * 2 + 1]);
            og[row * 128 + h * 16 + n2 * 4 + tig] = v0;
            og[(row + 8) * 128 + h * 16 + n2 * 4 + tig] = v1;
        }
    }
}

// ---------------- C: HMMA out-proj + LN2 + HMMA FFN + residual + scatter ----------------
// dynamic smem (u32): ybuf [0, 8448) f32 pitch 33 (woutu bf16 overlays start)
//                     lnsh [8448, 13568) bf16x2 pitch 20
__global__ void __launch_bounds__(256, 2) epi_kernel(
    const float* __restrict__ x, const float* __restrict__ bout,
    const float* __restrict__ g2, const float* __restrict__ be2,
    const float* __restrict__ fb1, const float* __restrict__ fb2,
    float* __restrict__ out) {
    extern __shared__ __align__(16) unsigned esmem[];
    float* ybuf = (float*)esmem;
    unsigned* lnsh = esmem + 8448;
    unsigned* woutu = esmem;          // [32][132] bf16x2, overlays ybuf

    int tid = threadIdx.x, wid = tid >> 5, lane = tid & 31;
    int b = blockIdx.x;

    {
        int idx = tid;
#pragma unroll
        for (int u = 0; u < 16; u++) {
            int o = idx >> 7, c = idx & 127;
            woutu[o * 132 + c] = g_woutb[idx];
            idx += 256;
        }
    }
    __syncthreads();

    int r4 = lane >> 2, tig = lane & 3;
    int mi = wid * 32;
    unsigned wbase = smem_u32(woutu);
    int lrow = lane & 7, lmat = lane >> 3;
    const unsigned* ag = g_attb + (size_t)b * 256 * 128;

    float yacc[2][4][4];
#pragma unroll
    for (int m = 0; m < 2; m++)
#pragma unroll
        for (int n = 0; n < 4; n++)
#pragma unroll
            for (int e = 0; e < 4; e++) yacc[m][n][e] = 0.f;

    for (int sp = 0; sp < 8; sp++) {
        unsigned br[4][4];
#pragma unroll
        for (int n0i = 0; n0i < 4; n0i++)
            ldm_x4(br[n0i], wbase + (((n0i * 8 + lrow) * 132 + (4 * sp + lmat) * 4) << 2));
        unsigned af0[2][4], af1[2][4];
#pragma unroll
        for (int m = 0; m < 2; m++) {
            int rw = mi + m * 16 + r4;
            const unsigned* arow = ag + rw * 128 + sp * 16 + tig;
            const unsigned* arow8 = ag + (rw + 8) * 128 + sp * 16 + tig;
            af0[m][0] = arow[0];  af0[m][1] = arow8[0];
            af0[m][2] = arow[4];  af0[m][3] = arow8[4];
            af1[m][0] = arow[8];  af1[m][1] = arow8[8];
            af1[m][2] = arow[12]; af1[m][3] = arow8[12];
        }
#pragma unroll
        for (int m = 0; m < 2; m++)
#pragma unroll
            for (int n0i = 0; n0i < 4; n0i++) {
                mma_bf16(yacc[m][n0i], af0[m], br[n0i][0], br[n0i][1]);
                mma_bf16(yacc[m][n0i], af1[m], br[n0i][2], br[n0i][3]);
            }
    }
    __syncthreads();
#pragma unroll
    for (int m = 0; m < 2; m++) {
        int rw = mi + m * 16 + r4;
#pragma unroll
        for (int n0i = 0; n0i < 4; n0i++) {
            int col = n0i * 8 + 2 * tig;
            ybuf[rw * 33 + col]           = yacc[m][n0i][0];
            ybuf[rw * 33 + col + 1]       = yacc[m][n0i][1];
            ybuf[(rw + 8) * 33 + col]     = yacc[m][n0i][2];
            ybuf[(rw + 8) * 33 + col + 1] = yacc[m][n0i][3];
        }
    }
    __syncthreads();

    int s = b * 256 + tid;
    int orig = (int)(g_sort[s] & 0xffffffffULL);
    float x2[32];
    const float4* xp = (const float4*)(x + orig * 32);
#pragma unroll
    for (int q8 = 0; q8 < 8; q8++) {
        float4 t = xp[q8];
        x2[4 * q8]     = t.x + ybuf[tid * 33 + 4 * q8]     + bout[4 * q8];
        x2[4 * q8 + 1] = t.y + ybuf[tid * 33 + 4 * q8 + 1] + bout[4 * q8 + 1];
        x2[4 * q8 + 2] = t.z + ybuf[tid * 33 + 4 * q8 + 2] + bout[4 * q8 + 2];
        x2[4 * q8 + 3] = t.w + ybuf[tid * 33 + 4 * q8 + 3] + bout[4 * q8 + 3];
    }
    float mu2 = 0.f;
#pragma unroll
    for (int d = 0; d < 32; d++) mu2 += x2[d];
    mu2 *= (1.f / 32.f);
    float var2 = 0.f;
#pragma unroll
    for (int d = 0; d < 32; d++) { float c = x2[d] - mu2; var2 = fmaf(c, c, var2); }
    var2 *= (1.f / 32.f);
    float inv2 = rsqrtf(var2 + 1e-5f);
#pragma unroll
    for (int c = 0; c < 16; c++) {
        float l0 = (x2[2 * c]     - mu2) * inv2 * g2[2 * c]     + be2[2 * c];
        float l1 = (x2[2 * c + 1] - mu2) * inv2 * g2[2 * c + 1] + be2[2 * c + 1];
        lnsh[tid * 20 + c] = pack_bf16x2(l0, l1);
    }
    __syncthreads();

    unsigned la[2][2][4];
#pragma unroll
    for (int m = 0; m < 2; m++)
#pragma unroll
        for (int ks = 0; ks < 2; ks++) {
            int rw = mi + r4 + m * 16;
            la[m][ks][0] = lnsh[rw * 20 + ks * 8 + tig];
            la[m][ks][1] = lnsh[(rw + 8) * 20 + ks * 8 + tig];
            la[m][ks][2] = lnsh[rw * 20 + ks * 8 + tig + 4];
            la[m][ks][3] = lnsh[(rw + 8) * 20 + ks * 8 + tig + 4];
        }

    unsigned hA[2][2][4];
    {
        float hacc[2][4][4];
#pragma unroll
        for (int n0i = 0; n0i < 4; n0i++) {
            int wrow = (n0i * 8 + r4) * 16 + tig;
            unsigned b00 = g_wffb[wrow], b01 = g_wffb[wrow + 4];
            unsigned b10 = g_wffb[wrow + 8], b11 = g_wffb[wrow + 12];
#pragma unroll
            for (int m = 0; m < 2; m++) {
#pragma unroll
                for (int e = 0; e < 4; e++) hacc[m][n0i][e] = 0.f;
                mma_bf16(hacc[m][n0i], la[m][0], b00, b01);
                mma_bf16(hacc[m][n0i], la[m][1], b10, b11);
            }
        }
#pragma unroll
        for (int n0i = 0; n0i < 4; n0i++) {
            int c0 = n0i * 8 + 2 * tig;
            float f0 = fb1[c0], f1 = fb1[c0 + 1];
#pragma unroll
            for (int m = 0; m < 2; m++) {
                hacc[m][n0i][0] = fmaxf(hacc[m][n0i][0] + f0, 0.f);
                hacc[m][n0i][1] = fmaxf(hacc[m][n0i][1] + f1, 0.f);
                hacc[m][n0i][2] = fmaxf(hacc[m][n0i][2] + f0, 0.f);
                hacc[m][n0i][3] = fmaxf(hacc[m][n0i][3] + f1, 0.f);
            }
        }
#pragma unroll
        for (int m = 0; m < 2; m++)
#pragma unroll
            for (int ks = 0; ks < 2; ks++) {
                hA[m][ks][0] = pack_bf16x2(hacc[m][2 * ks][0], hacc[m][2 * ks][1]);
                hA[m][ks][1] = pack_bf16x2(hacc[m][2 * ks][2], hacc[m][2 * ks][3]);
                hA[m][ks][2] = pack_bf16x2(hacc[m][2 * ks + 1][0], hacc[m][2 * ks + 1][1]);
                hA[m][ks][3] = pack_bf16x2(hacc[m][2 * ks + 1][2], hacc[m][2 * ks + 1][3]);
            }
    }

    float facc[2][4][4];
#pragma unroll
    for (int n0i = 0; n0i < 4; n0i++) {
        int wrow = 512 + (n0i * 8 + r4) * 16 + tig;
        unsigned b00 = g_wffb[wrow], b01 = g_wffb[wrow + 4];
        unsigned b10 = g_wffb[wrow + 8], b11 = g_wffb[wrow + 12];
#pragma unroll
        for (int m = 0; m < 2; m++) {
#pragma unroll
            for (int e = 0; e < 4; e++) facc[m][n0i][e] = 0.f;
            mma_bf16(facc[m][n0i], hA[m][0], b00, b01);
            mma_bf16(facc[m][n0i], hA[m][1], b10, b11);
        }
    }
#pragma unroll
    for (int m = 0; m < 2; m++) {
        int rw = mi + m * 16 + r4;
#pragma unroll
        for (int n0i = 0; n0i < 4; n0i++) {
            int col = n0i * 8 + 2 * tig;
            ybuf[rw * 33 + col]           = facc[m][n0i][0];
            ybuf[rw * 33 + col + 1]       = facc[m][n0i][1];
            ybuf[(rw + 8) * 33 + col]     = facc[m][n0i][2];
            ybuf[(rw + 8) * 33 + col + 1] = facc[m][n0i][3];
        }
    }
    __syncthreads();

    float4* op = (float4*)(out + orig * 32);
#pragma unroll
    for (int q8 = 0; q8 < 8; q8++) {
        float4 t;
        t.x = x2[4 * q8]     + ybuf[tid * 33 + 4 * q8]     + fb2[4 * q8];
        t.y = x2[4 * q8 + 1] + ybuf[tid * 33 + 4 * q8 + 1] + fb2[4 * q8 + 1];
        t.z = x2[4 * q8 + 2] + ybuf[tid * 33 + 4 * q8 + 2] + fb2[4 * q8 + 2];
        t.w = x2[4 * q8 + 3] + ybuf[tid * 33 + 4 * q8 + 3] + fb2[4 * q8 + 3];
        op[q8] = t;
    }
}

// ---------------- host launcher ----------------
#define ATTN_SMEM (16128 * 4)
#define EPI_SMEM (13568 * 4)

extern "C" void kernel_launch(void* const* d_in, const int* in_sizes, int n_in,
                              void* d_out, int out_size) {
    const float* x      = (const float*)d_in[0];
    const float* coords = (const float*)d_in[1];
    const float* wq     = (const float*)d_in[2];
    const float* wk     = (const float*)d_in[3];
    const float* wv     = (const float*)d_in[4];
    const float* wrpe   = (const float*)d_in[5];
    const float* wout   = (const float*)d_in[6];
    const float* bout   = (const float*)d_in[7];
    const float* g1     = (const float*)d_in[8];
    const float* be1    = (const float*)d_in[9];
    const float* g2     = (const float*)d_in[10];
    const float* be2    = (const float*)d_in[11];
    const float* fw1    = (const float*)d_in[12];
    const float* fb1    = (const float*)d_in[13];
    const float* fw2    = (const float*)d_in[14];
    const float* fb2    = (const float*)d_in[15];
    float* out = (float*)d_out;

    cudaFuncSetAttribute(attn_kernel, cudaFuncAttributeMaxDynamicSharedMemorySize, ATTN_SMEM);
    cudaFuncSetAttribute(epi_kernel, cudaFuncAttributeMaxDynamicSharedMemorySize, EPI_SMEM);

    sort_hist<<<64, 1024>>>(coords);
    sort_prefix_prep<<<1, 1024>>>(wq, wk, wv, wout, wrpe, fw1, fw2);
    sort_scatter<<<256, 256>>>(coords);
    sort_buckets<<<256, 256>>>();
    ln1_kernel<<<NBLK, 256>>>(x, coords, g1, be1);
    attn_kernel<<<NBLK * NH, 256, ATTN_SMEM>>>();
    epi_kernel<<<NBLK, 256, EPI_SMEM>>>(x, bout, g2, be2, fb1, fb2, out);
}